// round 16
// baseline (speedup 1.0000x reference)
#include <cuda_runtime.h>
#include <cuda_fp16.h>

#define N_USERS 100000
#define N_ITEMS 50000
#define N_NODES 150000
#define DIM 128
#define N_EDGES 4800000
#define NV4 (N_NODES * 32)
#define SCAN_B 1024
#define SCAN_G ((N_NODES + SCAN_B - 1) / SCAN_B)   // 147

// ---- scratch (static device globals; no runtime allocation) ----
__device__ uint2 g_agg[NV4];           // 38.4 MB fp16 node matrix (ping)
__device__ uint2 g_side[NV4];          // 38.4 MB fp16 node matrix (pong)
__device__ int2  g_edge[N_EDGES];      // packed (col, val-bits), 38.4 MB
__device__ int   g_counts[N_NODES];
__device__ int   g_offsets[N_NODES + 1];
__device__ int   g_cursor[N_NODES];
__device__ int   g_bsum[SCAN_G];

static __device__ __forceinline__ uint2 pack_half4(float4 a) {
    __half2 h0 = __floats2half2_rn(a.x, a.y);
    __half2 h1 = __floats2half2_rn(a.z, a.w);
    uint2 r;
    r.x = *reinterpret_cast<unsigned int*>(&h0);
    r.y = *reinterpret_cast<unsigned int*>(&h1);
    return r;
}

// ---- init: agg(h16) = concat(embed); out[:,0,:] = t*embed (runs on side stream) ----
__global__ void k_init(const float* __restrict__ ue, const float* __restrict__ ie,
                       const float* __restrict__ ut, const float* __restrict__ it,
                       float4* __restrict__ out) {
    int idx = blockIdx.x * blockDim.x + threadIdx.x;
    if (idx >= NV4) return;
    int node = idx >> 5;
    int lane = idx & 31;
    float4 x;
    float t;
    if (node < N_USERS) {
        x = __ldcs(&reinterpret_cast<const float4*>(ue)[node * 32 + lane]);
        t = __ldg(ut + node);
    } else {
        int n2 = node - N_USERS;
        x = __ldcs(&reinterpret_cast<const float4*>(ie)[n2 * 32 + lane]);
        t = __ldg(it + n2);
    }
    g_agg[idx] = pack_half4(x);
    __stcs(&out[(node * 4 + 0) * 32 + lane],
           make_float4(t * x.x, t * x.y, t * x.z, t * x.w));
}

__global__ void k_zero() {
    int i = blockIdx.x * blockDim.x + threadIdx.x;
    if (i < N_NODES) g_counts[i] = 0;
}

// hist: default-policy row loads keep rows (19.2 MB) L2-resident for scatter's re-read
__global__ void k_hist(const int* __restrict__ rows) {
    int e = blockIdx.x * blockDim.x + threadIdx.x;
    if (e < N_EDGES) atomicAdd(&g_counts[rows[e]], 1);
}

// block-local exclusive scan over counts
__global__ void k_scan1() {
    __shared__ int sh[SCAN_B];
    int tid = threadIdx.x;
    int gid = blockIdx.x * SCAN_B + tid;
    int v = (gid < N_NODES) ? g_counts[gid] : 0;
    sh[tid] = v;
    __syncthreads();
#pragma unroll
    for (int off = 1; off < SCAN_B; off <<= 1) {
        int t = (tid >= off) ? sh[tid - off] : 0;
        __syncthreads();
        if (tid >= off) sh[tid] += t;
        __syncthreads();
    }
    int incl = sh[tid];
    if (gid < N_NODES) g_offsets[gid] = incl - v;
    if (tid == SCAN_B - 1) g_bsum[blockIdx.x] = incl;
}

// fused: every block redundantly scans the 147 block sums, then applies its offset
__global__ void k_scan23() {
    __shared__ int sh[256];
    int tid = threadIdx.x;
    if (tid < 256) sh[tid] = (tid < SCAN_G) ? g_bsum[tid] : 0;
    __syncthreads();
#pragma unroll
    for (int off = 1; off < 256; off <<= 1) {
        int t = 0;
        if (tid < 256 && tid >= off) t = sh[tid - off];
        __syncthreads();
        if (tid < 256 && tid >= off) sh[tid] += t;
        __syncthreads();
    }
    int boff = (blockIdx.x == 0) ? 0 : sh[blockIdx.x - 1];   // exclusive block offset
    int gid = blockIdx.x * SCAN_B + tid;
    if (gid < N_NODES) {
        int o = g_offsets[gid] + boff;
        g_offsets[gid] = o;
        g_cursor[gid]  = o;
    }
    if (gid == 0) g_offsets[N_NODES] = N_EDGES;
}

__global__ void k_scatter(const int* __restrict__ rows, const int* __restrict__ cols,
                          const float* __restrict__ vals) {
    int e = blockIdx.x * blockDim.x + threadIdx.x;
    if (e >= N_EDGES) return;
    int r = rows[e];                              // L2 hit (resident since hist)
    int p = atomicAdd(&g_cursor[r], 1);
    __stcs(&g_edge[p], make_int2(__ldcs(cols + e), __float_as_int(__ldcs(vals + e))));
}

// ---- SpMM: one warp per row; lane owns 4 dims; fp32 accumulate ----
__global__ void __launch_bounds__(256) k_spmm(int dir, int hop,
                                              const float* __restrict__ ut,
                                              const float* __restrict__ it,
                                              float4* __restrict__ out) {
    int w = (blockIdx.x * blockDim.x + threadIdx.x) >> 5;
    if (w >= N_NODES) return;
    int lane = threadIdx.x & 31;

    const uint2* __restrict__ x = dir ? g_side : g_agg;
    uint2* __restrict__       y = dir ? g_agg  : g_side;

    int s = g_offsets[w];
    int e = g_offsets[w + 1];

    float4 a0 = make_float4(0.f, 0.f, 0.f, 0.f);
    float4 a1 = make_float4(0.f, 0.f, 0.f, 0.f);

    int i = s;
    if ((i & 1) && i < e) {                        // align for int4 2-edge loads
        int2 e0 = __ldcs(&g_edge[i]);
        uint2 r0 = x[e0.x * 32 + lane];
        float v0 = __int_as_float(e0.y);
        float2 f00 = __half22float2(*reinterpret_cast<const __half2*>(&r0.x));
        float2 f01 = __half22float2(*reinterpret_cast<const __half2*>(&r0.y));
        a0.x = fmaf(v0, f00.x, a0.x); a0.y = fmaf(v0, f00.y, a0.y);
        a0.z = fmaf(v0, f01.x, a0.z); a0.w = fmaf(v0, f01.y, a0.w);
        i++;
    }
    const int4* ep = reinterpret_cast<const int4*>(g_edge);
    for (; i + 2 <= e; i += 2) {
        int4 p = __ldcs(&ep[i >> 1]);              // two packed edges, uniform LDG.128
        uint2 r0 = x[p.x * 32 + lane];
        uint2 r1 = x[p.z * 32 + lane];
        float v0 = __int_as_float(p.y);
        float v1 = __int_as_float(p.w);
        float2 f00 = __half22float2(*reinterpret_cast<const __half2*>(&r0.x));
        float2 f01 = __half22float2(*reinterpret_cast<const __half2*>(&r0.y));
        float2 f10 = __half22float2(*reinterpret_cast<const __half2*>(&r1.x));
        float2 f11 = __half22float2(*reinterpret_cast<const __half2*>(&r1.y));
        a0.x = fmaf(v0, f00.x, a0.x); a0.y = fmaf(v0, f00.y, a0.y);
        a0.z = fmaf(v0, f01.x, a0.z); a0.w = fmaf(v0, f01.y, a0.w);
        a1.x = fmaf(v1, f10.x, a1.x); a1.y = fmaf(v1, f10.y, a1.y);
        a1.z = fmaf(v1, f11.x, a1.z); a1.w = fmaf(v1, f11.y, a1.w);
    }
    if (i < e) {
        int2 e0 = __ldcs(&g_edge[i]);
        uint2 r0 = x[e0.x * 32 + lane];
        float v0 = __int_as_float(e0.y);
        float2 f00 = __half22float2(*reinterpret_cast<const __half2*>(&r0.x));
        float2 f01 = __half22float2(*reinterpret_cast<const __half2*>(&r0.y));
        a0.x = fmaf(v0, f00.x, a0.x); a0.y = fmaf(v0, f00.y, a0.y);
        a0.z = fmaf(v0, f01.x, a0.z); a0.w = fmaf(v0, f01.y, a0.w);
    }
    float4 acc = make_float4(a0.x + a1.x, a0.y + a1.y, a0.z + a1.z, a0.w + a1.w);

    if (hop != 3)                       // last hop: nothing consumes y
        y[w * 32 + lane] = pack_half4(acc);

    float t = (w < N_USERS) ? __ldg(ut + w) : __ldg(it + (w - N_USERS));
    float coef = t;
    float d = 1.0f - t;
    for (int k = 0; k < hop; k++) coef *= d;   // t * (1-t)^hop

    __stcs(&out[(w * 4 + hop) * 32 + lane],
           make_float4(coef * acc.x, coef * acc.y, coef * acc.z, coef * acc.w));
}

extern "C" void kernel_launch(void* const* d_in, const int* in_sizes, int n_in,
                              void* d_out, int out_size) {
    const float* ue   = (const float*)d_in[0];
    const float* ie   = (const float*)d_in[1];
    const float* ut   = (const float*)d_in[2];
    const float* it   = (const float*)d_in[3];
    const float* vals = (const float*)d_in[4];
    const int*   rows = (const int*)d_in[5];
    const int*   cols = (const int*)d_in[6];
    float4* out = (float4*)d_out;

    // one-time side stream + events (host resources only; no device memory)
    static cudaStream_t s_side = nullptr;
    static cudaEvent_t  ev_fork = nullptr, ev_join = nullptr;
    if (s_side == nullptr) {
        cudaStreamCreateWithFlags(&s_side, cudaStreamNonBlocking);
        cudaEventCreateWithFlags(&ev_fork, cudaEventDisableTiming);
        cudaEventCreateWithFlags(&ev_join, cudaEventDisableTiming);
    }

    const int TB = 256;
    int spmm_blocks = (N_NODES * 32 + TB - 1) / TB;

    // fork: init (agg + hop-0 output) runs concurrently with the CSR build
    cudaEventRecord(ev_fork, 0);
    cudaStreamWaitEvent(s_side, ev_fork, 0);
    k_init<<<(NV4 + TB - 1) / TB, TB, 0, s_side>>>(ue, ie, ut, it, out);
    cudaEventRecord(ev_join, s_side);

    // CSR build (counting sort by row) on the main stream
    k_zero<<<(N_NODES + TB - 1) / TB, TB>>>();
    k_hist<<<(N_EDGES + TB - 1) / TB, TB>>>(rows);
    k_scan1<<<SCAN_G, SCAN_B>>>();
    k_scan23<<<SCAN_G, SCAN_B>>>();
    k_scatter<<<(N_EDGES + TB - 1) / TB, TB>>>(rows, cols, vals);

    // join: hops need g_agg from init
    cudaStreamWaitEvent(0, ev_join, 0);

    k_spmm<<<spmm_blocks, TB>>>(0, 1, ut, it, out);
    k_spmm<<<spmm_blocks, TB>>>(1, 2, ut, it, out);
    k_spmm<<<spmm_blocks, TB>>>(0, 3, ut, it, out);
}

// round 17
// speedup vs baseline: 1.0108x; 1.0108x over previous
#include <cuda_runtime.h>
#include <cuda_fp16.h>

#define N_USERS 100000
#define N_ITEMS 50000
#define N_NODES 150000
#define DIM 128
#define N_EDGES 4800000
#define NV4 (N_NODES * 32)
#define SCAN_B 1024
#define SCAN_G ((N_NODES + SCAN_B - 1) / SCAN_B)   // 147

// ---- scratch (static device globals; no runtime allocation) ----
__device__ uint2 g_agg[NV4];           // 38.4 MB fp16 node matrix (ping)
__device__ uint2 g_side[NV4];          // 38.4 MB fp16 node matrix (pong)
__device__ int2  g_edge[N_EDGES];      // packed (col, val-bits), 38.4 MB
__device__ int   g_counts[N_NODES];
__device__ int   g_offsets[N_NODES + 1];
__device__ int   g_cursor[N_NODES];
__device__ int   g_bsum[SCAN_G];

static __device__ __forceinline__ uint2 pack_half4(float4 a) {
    __half2 h0 = __floats2half2_rn(a.x, a.y);
    __half2 h1 = __floats2half2_rn(a.z, a.w);
    uint2 r;
    r.x = *reinterpret_cast<unsigned int*>(&h0);
    r.y = *reinterpret_cast<unsigned int*>(&h1);
    return r;
}

// ---- init: agg(h16) = concat(embed); out[:,0,:] = t*embed; zero counts ----
__global__ void k_init(const float* __restrict__ ue, const float* __restrict__ ie,
                       const float* __restrict__ ut, const float* __restrict__ it,
                       float4* __restrict__ out) {
    int idx = blockIdx.x * blockDim.x + threadIdx.x;
    if (idx < N_NODES) g_counts[idx] = 0;
    if (idx >= NV4) return;
    int node = idx >> 5;
    int lane = idx & 31;
    float4 x;
    float t;
    if (node < N_USERS) {
        x = __ldcs(&reinterpret_cast<const float4*>(ue)[node * 32 + lane]);
        t = __ldg(ut + node);
    } else {
        int n2 = node - N_USERS;
        x = __ldcs(&reinterpret_cast<const float4*>(ie)[n2 * 32 + lane]);
        t = __ldg(it + n2);
    }
    g_agg[idx] = pack_half4(x);
    __stcs(&out[(node * 4 + 0) * 32 + lane],
           make_float4(t * x.x, t * x.y, t * x.z, t * x.w));
}

// hist: default-policy row loads keep rows (19.2 MB) L2-resident for scatter's re-read
__global__ void k_hist(const int* __restrict__ rows) {
    int e = blockIdx.x * blockDim.x + threadIdx.x;
    if (e < N_EDGES) atomicAdd(&g_counts[rows[e]], 1);
}

// block-local exclusive scan over counts
__global__ void k_scan1() {
    __shared__ int sh[SCAN_B];
    int tid = threadIdx.x;
    int gid = blockIdx.x * SCAN_B + tid;
    int v = (gid < N_NODES) ? g_counts[gid] : 0;
    sh[tid] = v;
    __syncthreads();
#pragma unroll
    for (int off = 1; off < SCAN_B; off <<= 1) {
        int t = (tid >= off) ? sh[tid - off] : 0;
        __syncthreads();
        if (tid >= off) sh[tid] += t;
        __syncthreads();
    }
    int incl = sh[tid];
    if (gid < N_NODES) g_offsets[gid] = incl - v;
    if (tid == SCAN_B - 1) g_bsum[blockIdx.x] = incl;
}

// fused: every block redundantly scans the 147 block sums, then applies its offset
__global__ void k_scan23() {
    __shared__ int sh[256];
    int tid = threadIdx.x;
    if (tid < 256) sh[tid] = (tid < SCAN_G) ? g_bsum[tid] : 0;
    __syncthreads();
#pragma unroll
    for (int off = 1; off < 256; off <<= 1) {
        int t = 0;
        if (tid < 256 && tid >= off) t = sh[tid - off];
        __syncthreads();
        if (tid < 256 && tid >= off) sh[tid] += t;
        __syncthreads();
    }
    int boff = (blockIdx.x == 0) ? 0 : sh[blockIdx.x - 1];   // exclusive block offset
    int gid = blockIdx.x * SCAN_B + tid;
    if (gid < N_NODES) {
        int o = g_offsets[gid] + boff;
        g_offsets[gid] = o;
        g_cursor[gid]  = o;
    }
    if (gid == 0) g_offsets[N_NODES] = N_EDGES;
}

// scatter: 2 edges per thread; paired input loads; rows hit L2 (resident since hist)
__global__ void k_scatter(const int2* __restrict__ rows2, const int2* __restrict__ cols2,
                          const float2* __restrict__ vals2) {
    int i = blockIdx.x * blockDim.x + threadIdx.x;
    if (i >= N_EDGES / 2) return;
    int2   r = rows2[i];
    int2   c = __ldcs(&cols2[i]);
    float2 v = __ldcs(&vals2[i]);
    int p0 = atomicAdd(&g_cursor[r.x], 1);
    int p1 = atomicAdd(&g_cursor[r.y], 1);
    __stcs(&g_edge[p0], make_int2(c.x, __float_as_int(v.x)));
    __stcs(&g_edge[p1], make_int2(c.y, __float_as_int(v.y)));
}

// ---- SpMM: one warp per row; lane owns 4 dims; fp32 accumulate ----
__global__ void __launch_bounds__(256) k_spmm(int dir, int hop,
                                              const float* __restrict__ ut,
                                              const float* __restrict__ it,
                                              float4* __restrict__ out) {
    int w = (blockIdx.x * blockDim.x + threadIdx.x) >> 5;
    if (w >= N_NODES) return;
    int lane = threadIdx.x & 31;

    const uint2* __restrict__ x = dir ? g_side : g_agg;
    uint2* __restrict__       y = dir ? g_agg  : g_side;

    int s = g_offsets[w];
    int e = g_offsets[w + 1];

    float4 a0 = make_float4(0.f, 0.f, 0.f, 0.f);
    float4 a1 = make_float4(0.f, 0.f, 0.f, 0.f);

    int i = s;
    if ((i & 1) && i < e) {                        // align for int4 2-edge loads
        int2 e0 = __ldcs(&g_edge[i]);
        uint2 r0 = x[e0.x * 32 + lane];
        float v0 = __int_as_float(e0.y);
        float2 f00 = __half22float2(*reinterpret_cast<const __half2*>(&r0.x));
        float2 f01 = __half22float2(*reinterpret_cast<const __half2*>(&r0.y));
        a0.x = fmaf(v0, f00.x, a0.x); a0.y = fmaf(v0, f00.y, a0.y);
        a0.z = fmaf(v0, f01.x, a0.z); a0.w = fmaf(v0, f01.y, a0.w);
        i++;
    }
    const int4* ep = reinterpret_cast<const int4*>(g_edge);
    for (; i + 2 <= e; i += 2) {
        int4 p = __ldcs(&ep[i >> 1]);              // two packed edges, uniform LDG.128
        uint2 r0 = x[p.x * 32 + lane];
        uint2 r1 = x[p.z * 32 + lane];
        float v0 = __int_as_float(p.y);
        float v1 = __int_as_float(p.w);
        float2 f00 = __half22float2(*reinterpret_cast<const __half2*>(&r0.x));
        float2 f01 = __half22float2(*reinterpret_cast<const __half2*>(&r0.y));
        float2 f10 = __half22float2(*reinterpret_cast<const __half2*>(&r1.x));
        float2 f11 = __half22float2(*reinterpret_cast<const __half2*>(&r1.y));
        a0.x = fmaf(v0, f00.x, a0.x); a0.y = fmaf(v0, f00.y, a0.y);
        a0.z = fmaf(v0, f01.x, a0.z); a0.w = fmaf(v0, f01.y, a0.w);
        a1.x = fmaf(v1, f10.x, a1.x); a1.y = fmaf(v1, f10.y, a1.y);
        a1.z = fmaf(v1, f11.x, a1.z); a1.w = fmaf(v1, f11.y, a1.w);
    }
    if (i < e) {
        int2 e0 = __ldcs(&g_edge[i]);
        uint2 r0 = x[e0.x * 32 + lane];
        float v0 = __int_as_float(e0.y);
        float2 f00 = __half22float2(*reinterpret_cast<const __half2*>(&r0.x));
        float2 f01 = __half22float2(*reinterpret_cast<const __half2*>(&r0.y));
        a0.x = fmaf(v0, f00.x, a0.x); a0.y = fmaf(v0, f00.y, a0.y);
        a0.z = fmaf(v0, f01.x, a0.z); a0.w = fmaf(v0, f01.y, a0.w);
    }
    float4 acc = make_float4(a0.x + a1.x, a0.y + a1.y, a0.z + a1.z, a0.w + a1.w);

    if (hop != 3)                       // last hop: nothing consumes y
        y[w * 32 + lane] = pack_half4(acc);

    float t = (w < N_USERS) ? __ldg(ut + w) : __ldg(it + (w - N_USERS));
    float coef = t;
    float d = 1.0f - t;
    for (int k = 0; k < hop; k++) coef *= d;   // t * (1-t)^hop

    __stcs(&out[(w * 4 + hop) * 32 + lane],
           make_float4(coef * acc.x, coef * acc.y, coef * acc.z, coef * acc.w));
}

extern "C" void kernel_launch(void* const* d_in, const int* in_sizes, int n_in,
                              void* d_out, int out_size) {
    const float* ue   = (const float*)d_in[0];
    const float* ie   = (const float*)d_in[1];
    const float* ut   = (const float*)d_in[2];
    const float* it   = (const float*)d_in[3];
    const float* vals = (const float*)d_in[4];
    const int*   rows = (const int*)d_in[5];
    const int*   cols = (const int*)d_in[6];
    float4* out = (float4*)d_out;

    const int TB = 256;

    k_init<<<(NV4 + TB - 1) / TB, TB>>>(ue, ie, ut, it, out);

    // CSR build (counting sort by row)
    k_hist<<<(N_EDGES + TB - 1) / TB, TB>>>(rows);
    k_scan1<<<SCAN_G, SCAN_B>>>();
    k_scan23<<<SCAN_G, SCAN_B>>>();
    k_scatter<<<(N_EDGES / 2 + TB - 1) / TB, TB>>>((const int2*)rows, (const int2*)cols,
                                                   (const float2*)vals);

    // 3 propagation hops
    int spmm_blocks = (N_NODES * 32 + TB - 1) / TB;
    k_spmm<<<spmm_blocks, TB>>>(0, 1, ut, it, out);
    k_spmm<<<spmm_blocks, TB>>>(1, 2, ut, it, out);
    k_spmm<<<spmm_blocks, TB>>>(0, 3, ut, it, out);
}